// round 14
// baseline (speedup 1.0000x reference)
#include <cuda_runtime.h>

// WarpDTI fused, 1 thread/voxel (R11 structure — best measured). R14 change:
// gather z-pair merged into one aligned LDG.128 per (channel, xy-corner) with
// a 4-tap hat-weight dot product (== exact z-lerp when z0..z1 fall inside the
// aligned window; the idx==3 remainder uses a predicated scalar load, ~25% of
// lanes). Cuts per-instruction L1 wavefronts ~30% — the modeled binding
// constraint (L1 pinned at ~63% across R11/R12/R13).

constexpr int HWD = 64 * 64 * 64;   // 262144 = 2^18

__global__ __launch_bounds__(256)
void warp_dti_kernel(const float* __restrict__ dti,
                     const float* __restrict__ ddf,
                     float* __restrict__ out,
                     int total)
{
    int idx = blockIdx.x * blockDim.x + threadIdx.x;
    if (idx >= total) return;

    int vox = idx & (HWD - 1);
    int b   = idx >> 18;
    int z   =  vox        & 63;
    int y   = (vox >> 6)  & 63;
    int x   =  vox >> 12;

    const float* u = ddf + (size_t)b * 3 * HWD;

    float u0 = __ldg(u +           vox);
    float u1 = __ldg(u +     HWD + vox);
    float u2 = __ldg(u + 2 * HWD + vox);

    // ---------- Jacobian J = I + du_i/dx_j (jnp.gradient semantics) --------
    float J00, J01, J02, J10, J11, J12, J20, J21, J22;
    {   // axis 0 (x), stride 4096
        int ip = (x < 63) ? x + 1 : 63;
        int im = (x > 0 ) ? x - 1 : 0;
        float s = (ip - im == 2) ? 0.5f : 1.0f;
        int op = (ip - x) << 12, om = (im - x) << 12;
        J00 = (__ldg(u +           vox + op) - __ldg(u +           vox + om)) * s;
        J10 = (__ldg(u + HWD     + vox + op) - __ldg(u + HWD     + vox + om)) * s;
        J20 = (__ldg(u + 2 * HWD + vox + op) - __ldg(u + 2 * HWD + vox + om)) * s;
    }
    {   // axis 1 (y), stride 64
        int ip = (y < 63) ? y + 1 : 63;
        int im = (y > 0 ) ? y - 1 : 0;
        float s = (ip - im == 2) ? 0.5f : 1.0f;
        int op = (ip - y) << 6, om = (im - y) << 6;
        J01 = (__ldg(u +           vox + op) - __ldg(u +           vox + om)) * s;
        J11 = (__ldg(u + HWD     + vox + op) - __ldg(u + HWD     + vox + om)) * s;
        J21 = (__ldg(u + 2 * HWD + vox + op) - __ldg(u + 2 * HWD + vox + om)) * s;
    }
    {   // axis 2 (z), stride 1
        int ip = (z < 63) ? z + 1 : 63;
        int im = (z > 0 ) ? z - 1 : 0;
        float s = (ip - im == 2) ? 0.5f : 1.0f;
        int op = ip - z, om = im - z;
        J02 = (__ldg(u +           vox + op) - __ldg(u +           vox + om)) * s;
        J12 = (__ldg(u + HWD     + vox + op) - __ldg(u + HWD     + vox + om)) * s;
        J22 = (__ldg(u + 2 * HWD + vox + op) - __ldg(u + 2 * HWD + vox + om)) * s;
    }
    J00 += 1.0f; J11 += 1.0f; J22 += 1.0f;

    // ---------- trilinear warp (border clamp, align_corners) ----------
    float cx = fminf(fmaxf(u0 + (float)x, 0.0f), 63.0f);
    float cy = fminf(fmaxf(u1 + (float)y, 0.0f), 63.0f);
    float cz = fminf(fmaxf(u2 + (float)z, 0.0f), 63.0f);
    float xf = floorf(cx), yf = floorf(cy), zf = floorf(cz);
    float fx = cx - xf,   fy = cy - yf;
    int x0 = (int)xf, y0 = (int)yf, z0 = (int)zf;
    int x1 = min(x0 + 1, 63), y1 = min(y0 + 1, 63);

    // z handled via aligned 4-float window [zb, zb+3], zb = z0 & ~3 (<= 60).
    // Hat weights reproduce the z-lerp exactly when z0,z1 are in the window
    // (idx = z0-zb <= 2). For idx == 3 the (z0+1) tap is the predicated extra
    // load with weight we = t-3 = fz; we > 0 implies z0 < 63 so zb+4 = z0+1
    // is in-bounds.
    int   zb = z0 & ~3;
    float t  = cz - (float)zb;
    float wz0 = fmaxf(0.0f, 1.0f - fabsf(t));
    float wz1 = fmaxf(0.0f, 1.0f - fabsf(t - 1.0f));
    float wz2 = fmaxf(0.0f, 1.0f - fabsf(t - 2.0f));
    float wz3 = fmaxf(0.0f, 1.0f - fabsf(t - 3.0f));
    float we  = fmaxf(0.0f, t - 3.0f);

    int bofs[4] = { (((x0 << 6) + y0) << 6) + zb,
                    (((x0 << 6) + y1) << 6) + zb,
                    (((x1 << 6) + y0) << 6) + zb,
                    (((x1 << 6) + y1) << 6) + zb };
    float wx0 = 1.0f - fx, wy0 = 1.0f - fy;
    float wk[4] = { wx0 * wy0, wx0 * fy, fx * wy0, fx * fy };

    float m[6] = {0.f, 0.f, 0.f, 0.f, 0.f, 0.f};
    const float* img = dti + (size_t)b * 6 * HWD;
    #pragma unroll
    for (int c = 0; c < 6; c++) {
        const float* p = img + (size_t)c * HWD;
        #pragma unroll
        for (int k = 0; k < 4; k++) {
            float4 v = __ldg((const float4*)(p + bofs[k]));
            float dz = v.x * wz0 + v.y * wz1 + v.z * wz2 + v.w * wz3;
            m[c] = fmaf(wk[k], dz, m[c]);
        }
    }
    if (we > 0.0f) {   // ~25% of lanes: z1 tap just past the aligned window
        #pragma unroll
        for (int c = 0; c < 6; c++) {
            const float* p = img + (size_t)c * HWD;
            #pragma unroll
            for (int k = 0; k < 4; k++)
                m[c] = fmaf(wk[k] * we, __ldg(p + bofs[k] + 4), m[c]);
        }
    }

    // ---------- polar factor R = U V^T ----------
    float X00 = J00, X01 = J01, X02 = J02;
    float X10 = J10, X11 = J11, X12 = J12;
    float X20 = J20, X21 = J21, X22 = J22;

    // 2 scaled Newton iterations (Frobenius mu, fast-math — self-correcting)
    #pragma unroll
    for (int it = 0; it < 2; ++it) {
        float C00 = X11 * X22 - X12 * X21;
        float C01 = X12 * X20 - X10 * X22;
        float C02 = X10 * X21 - X11 * X20;
        float C10 = X21 * X02 - X22 * X01;
        float C11 = X22 * X00 - X20 * X02;
        float C12 = X20 * X01 - X21 * X00;
        float C20 = X01 * X12 - X02 * X11;
        float C21 = X02 * X10 - X00 * X12;
        float C22 = X00 * X11 - X01 * X10;
        float det = X00 * C00 + X01 * C01 + X02 * C02;
        float adet = fmaxf(fabsf(det), 1e-12f);
        float sdet = (det < 0.0f) ? -adet : adet;
        float nX = X00*X00 + X01*X01 + X02*X02 + X10*X10 + X11*X11 + X12*X12
                 + X20*X20 + X21*X21 + X22*X22;
        float nC = C00*C00 + C01*C01 + C02*C02 + C10*C10 + C11*C11 + C12*C12
                 + C20*C20 + C21*C21 + C22*C22;
        float mu = exp2f(0.25f * __log2f(nC / nX)) * rsqrtf(adet);
        mu = fminf(fmaxf(mu, 1e-4f), 1e4f);
        float a = 0.5f * mu;
        float c = __fdividef(0.5f, mu * sdet);
        X00 = a * X00 + c * C00; X01 = a * X01 + c * C01; X02 = a * X02 + c * C02;
        X10 = a * X10 + c * C10; X11 = a * X11 + c * C11; X12 = a * X12 + c * C12;
        X20 = a * X20 + c * C20; X21 = a * X21 + c * C21; X22 = a * X22 + c * C22;
    }
    // 4 plain Newton iterations: X <- 0.5*(X + cof(X)/det)
    #pragma unroll
    for (int it = 0; it < 4; ++it) {
        float C00 = X11 * X22 - X12 * X21;
        float C01 = X12 * X20 - X10 * X22;
        float C02 = X10 * X21 - X11 * X20;
        float C10 = X21 * X02 - X22 * X01;
        float C11 = X22 * X00 - X20 * X02;
        float C12 = X20 * X01 - X21 * X00;
        float C20 = X01 * X12 - X02 * X11;
        float C21 = X02 * X10 - X00 * X12;
        float C22 = X00 * X11 - X01 * X10;
        float det = X00 * C00 + X01 * C01 + X02 * C02;
        float adet = fmaxf(fabsf(det), 1e-12f);
        float sdet = (det < 0.0f) ? -adet : adet;
        float c = __fdividef(0.5f, sdet);
        X00 = 0.5f * X00 + c * C00; X01 = 0.5f * X01 + c * C01; X02 = 0.5f * X02 + c * C02;
        X10 = 0.5f * X10 + c * C10; X11 = 0.5f * X11 + c * C11; X12 = 0.5f * X12 + c * C12;
        X20 = 0.5f * X20 + c * C20; X21 = 0.5f * X21 + c * C21; X22 = 0.5f * X22 + c * C22;
    }

    // ---------- S = R^T M R, lower triangle ----------
    float w0x = m[0]*X00 + m[1]*X10 + m[3]*X20;
    float w0y = m[1]*X00 + m[2]*X10 + m[4]*X20;
    float w0z = m[3]*X00 + m[4]*X10 + m[5]*X20;
    float w1x = m[0]*X01 + m[1]*X11 + m[3]*X21;
    float w1y = m[1]*X01 + m[2]*X11 + m[4]*X21;
    float w1z = m[3]*X01 + m[4]*X11 + m[5]*X21;
    float w2x = m[0]*X02 + m[1]*X12 + m[3]*X22;
    float w2y = m[1]*X02 + m[2]*X12 + m[4]*X22;
    float w2z = m[3]*X02 + m[4]*X12 + m[5]*X22;

    float S00 = X00*w0x + X10*w0y + X20*w0z;
    float S10 = X01*w0x + X11*w0y + X21*w0z;
    float S11 = X01*w1x + X11*w1y + X21*w1z;
    float S20 = X02*w0x + X12*w0y + X22*w0z;
    float S21 = X02*w1x + X12*w1y + X22*w1z;
    float S22 = X02*w2x + X12*w2y + X22*w2z;

    float* o = out + (size_t)b * 6 * HWD + vox;
    o[0]       = S00;
    o[HWD]     = S10;
    o[2 * HWD] = S11;
    o[3 * HWD] = S20;
    o[4 * HWD] = S21;
    o[5 * HWD] = S22;
}

extern "C" void kernel_launch(void* const* d_in, const int* in_sizes, int n_in,
                              void* d_out, int out_size)
{
    const float* dti = (const float*)d_in[0];
    const float* ddf = (const float*)d_in[1];
    int s0 = in_sizes[0], s1 = in_sizes[1];
    if (s0 < s1) { const float* t = dti; dti = ddf; ddf = t; int ts = s0; s0 = s1; s1 = ts; }
    int B = s1 / (3 * HWD);
    int total = B * HWD;
    int threads = 256;
    int blocks = (total + threads - 1) / threads;
    warp_dti_kernel<<<blocks, threads>>>(dti, ddf, (float*)d_out, total);
}

// round 15
// speedup vs baseline: 2.0572x; 2.0572x over previous
#include <cuda_runtime.h>
#include <cuda_fp16.h>

// WarpDTI fused — R11 structure (measured best: scalar planar gather, 4B/lane,
// z-contiguous lanes) with ONE change: dti is pre-packed into 3 planar __half2
// planes (channel pairs), halving gather instructions 48 -> 24 at an identical
// per-instruction L1 line footprint. J and R stay fp32; only M is fp16-quantized
// (expected rel_err ~2-3e-4 vs 1e-3 threshold).

constexpr int HWD  = 64 * 64 * 64;   // 262144 = 2^18
constexpr int MAXB = 2;

__device__ __half2 g_dti_h[(size_t)MAXB * 3 * HWD];   // 6.3 MB scratch

__global__ __launch_bounds__(256)
void pack_half_kernel(const float* __restrict__ dti, int total)
{
    int idx = blockIdx.x * blockDim.x + threadIdx.x;
    if (idx >= total) return;
    int vox = idx & (HWD - 1);
    int b   = idx >> 18;
    const float* p = dti + (size_t)b * 6 * HWD + vox;
    __half2* g = g_dti_h + (size_t)b * 3 * HWD;
    g[vox]           = __floats2half2_rn(__ldg(p),           __ldg(p +     HWD));
    g[HWD + vox]     = __floats2half2_rn(__ldg(p + 2 * HWD), __ldg(p + 3 * HWD));
    g[2 * HWD + vox] = __floats2half2_rn(__ldg(p + 4 * HWD), __ldg(p + 5 * HWD));
}

__global__ __launch_bounds__(256)
void warp_dti_kernel(const float* __restrict__ ddf,
                     float* __restrict__ out,
                     int total)
{
    int idx = blockIdx.x * blockDim.x + threadIdx.x;
    if (idx >= total) return;

    int vox = idx & (HWD - 1);
    int b   = idx >> 18;
    int z   =  vox        & 63;
    int y   = (vox >> 6)  & 63;
    int x   =  vox >> 12;

    const float* u = ddf + (size_t)b * 3 * HWD;

    float u0 = __ldg(u +           vox);
    float u1 = __ldg(u +     HWD + vox);
    float u2 = __ldg(u + 2 * HWD + vox);

    // ---------- Jacobian J = I + du_i/dx_j (jnp.gradient semantics) --------
    float J00, J01, J02, J10, J11, J12, J20, J21, J22;
    {   // axis 0 (x), stride 4096
        int ip = (x < 63) ? x + 1 : 63;
        int im = (x > 0 ) ? x - 1 : 0;
        float s = (ip - im == 2) ? 0.5f : 1.0f;
        int op = (ip - x) << 12, om = (im - x) << 12;
        J00 = (__ldg(u +           vox + op) - __ldg(u +           vox + om)) * s;
        J10 = (__ldg(u + HWD     + vox + op) - __ldg(u + HWD     + vox + om)) * s;
        J20 = (__ldg(u + 2 * HWD + vox + op) - __ldg(u + 2 * HWD + vox + om)) * s;
    }
    {   // axis 1 (y), stride 64
        int ip = (y < 63) ? y + 1 : 63;
        int im = (y > 0 ) ? y - 1 : 0;
        float s = (ip - im == 2) ? 0.5f : 1.0f;
        int op = (ip - y) << 6, om = (im - y) << 6;
        J01 = (__ldg(u +           vox + op) - __ldg(u +           vox + om)) * s;
        J11 = (__ldg(u + HWD     + vox + op) - __ldg(u + HWD     + vox + om)) * s;
        J21 = (__ldg(u + 2 * HWD + vox + op) - __ldg(u + 2 * HWD + vox + om)) * s;
    }
    {   // axis 2 (z), stride 1
        int ip = (z < 63) ? z + 1 : 63;
        int im = (z > 0 ) ? z - 1 : 0;
        float s = (ip - im == 2) ? 0.5f : 1.0f;
        int op = ip - z, om = im - z;
        J02 = (__ldg(u +           vox + op) - __ldg(u +           vox + om)) * s;
        J12 = (__ldg(u + HWD     + vox + op) - __ldg(u + HWD     + vox + om)) * s;
        J22 = (__ldg(u + 2 * HWD + vox + op) - __ldg(u + 2 * HWD + vox + om)) * s;
    }
    J00 += 1.0f; J11 += 1.0f; J22 += 1.0f;

    // ---------- trilinear warp (border clamp, align_corners) ----------
    float cx = fminf(fmaxf(u0 + (float)x, 0.0f), 63.0f);
    float cy = fminf(fmaxf(u1 + (float)y, 0.0f), 63.0f);
    float cz = fminf(fmaxf(u2 + (float)z, 0.0f), 63.0f);
    float xf = floorf(cx), yf = floorf(cy), zf = floorf(cz);
    float fx = cx - xf,   fy = cy - yf,   fz = cz - zf;
    int x0 = (int)xf, y0 = (int)yf, z0 = (int)zf;
    int x1 = min(x0 + 1, 63), y1 = min(y0 + 1, 63), z1 = min(z0 + 1, 63);

    int c000 = ((((x0 << 6) + y0) << 6)) + z0;
    int c001 = ((((x0 << 6) + y0) << 6)) + z1;
    int c010 = ((((x0 << 6) + y1) << 6)) + z0;
    int c011 = ((((x0 << 6) + y1) << 6)) + z1;
    int c100 = ((((x1 << 6) + y0) << 6)) + z0;
    int c101 = ((((x1 << 6) + y0) << 6)) + z1;
    int c110 = ((((x1 << 6) + y1) << 6)) + z0;
    int c111 = ((((x1 << 6) + y1) << 6)) + z1;

    float wx0 = 1.0f - fx, wy0 = 1.0f - fy, wz0 = 1.0f - fz;
    float w000 = wx0 * wy0 * wz0, w001 = wx0 * wy0 * fz;
    float w010 = wx0 * fy  * wz0, w011 = wx0 * fy  * fz;
    float w100 = fx  * wy0 * wz0, w101 = fx  * wy0 * fz;
    float w110 = fx  * fy  * wz0, w111 = fx  * fy  * fz;

    // ---------- gather: 3 half2 planes x 8 corners = 24 LDG.32 ----------
    float m[6];
    const __half2* img = g_dti_h + (size_t)b * 3 * HWD;
    #pragma unroll
    for (int pl = 0; pl < 3; pl++) {
        const __half2* p = img + (size_t)pl * HWD;
        float2 v000 = __half22float2(__ldg(p + c000));
        float2 v001 = __half22float2(__ldg(p + c001));
        float2 v010 = __half22float2(__ldg(p + c010));
        float2 v011 = __half22float2(__ldg(p + c011));
        float2 v100 = __half22float2(__ldg(p + c100));
        float2 v101 = __half22float2(__ldg(p + c101));
        float2 v110 = __half22float2(__ldg(p + c110));
        float2 v111 = __half22float2(__ldg(p + c111));
        m[2 * pl]     = w000 * v000.x + w001 * v001.x + w010 * v010.x + w011 * v011.x
                      + w100 * v100.x + w101 * v101.x + w110 * v110.x + w111 * v111.x;
        m[2 * pl + 1] = w000 * v000.y + w001 * v001.y + w010 * v010.y + w011 * v011.y
                      + w100 * v100.y + w101 * v101.y + w110 * v110.y + w111 * v111.y;
    }

    // ---------- polar factor R = U V^T ----------
    float X00 = J00, X01 = J01, X02 = J02;
    float X10 = J10, X11 = J11, X12 = J12;
    float X20 = J20, X21 = J21, X22 = J22;

    // 2 scaled Newton iterations (Frobenius mu, fast-math — self-correcting)
    #pragma unroll
    for (int it = 0; it < 2; ++it) {
        float C00 = X11 * X22 - X12 * X21;
        float C01 = X12 * X20 - X10 * X22;
        float C02 = X10 * X21 - X11 * X20;
        float C10 = X21 * X02 - X22 * X01;
        float C11 = X22 * X00 - X20 * X02;
        float C12 = X20 * X01 - X21 * X00;
        float C20 = X01 * X12 - X02 * X11;
        float C21 = X02 * X10 - X00 * X12;
        float C22 = X00 * X11 - X01 * X10;
        float det = X00 * C00 + X01 * C01 + X02 * C02;
        float adet = fmaxf(fabsf(det), 1e-12f);
        float sdet = (det < 0.0f) ? -adet : adet;
        float nX = X00*X00 + X01*X01 + X02*X02 + X10*X10 + X11*X11 + X12*X12
                 + X20*X20 + X21*X21 + X22*X22;
        float nC = C00*C00 + C01*C01 + C02*C02 + C10*C10 + C11*C11 + C12*C12
                 + C20*C20 + C21*C21 + C22*C22;
        float mu = exp2f(0.25f * __log2f(nC / nX)) * rsqrtf(adet);
        mu = fminf(fmaxf(mu, 1e-4f), 1e4f);
        float a = 0.5f * mu;
        float c = __fdividef(0.5f, mu * sdet);
        X00 = a * X00 + c * C00; X01 = a * X01 + c * C01; X02 = a * X02 + c * C02;
        X10 = a * X10 + c * C10; X11 = a * X11 + c * C11; X12 = a * X12 + c * C12;
        X20 = a * X20 + c * C20; X21 = a * X21 + c * C21; X22 = a * X22 + c * C22;
    }
    // 4 plain Newton iterations: X <- 0.5*(X + cof(X)/det)
    #pragma unroll
    for (int it = 0; it < 4; ++it) {
        float C00 = X11 * X22 - X12 * X21;
        float C01 = X12 * X20 - X10 * X22;
        float C02 = X10 * X21 - X11 * X20;
        float C10 = X21 * X02 - X22 * X01;
        float C11 = X22 * X00 - X20 * X02;
        float C12 = X20 * X01 - X21 * X00;
        float C20 = X01 * X12 - X02 * X11;
        float C21 = X02 * X10 - X00 * X12;
        float C22 = X00 * X11 - X01 * X10;
        float det = X00 * C00 + X01 * C01 + X02 * C02;
        float adet = fmaxf(fabsf(det), 1e-12f);
        float sdet = (det < 0.0f) ? -adet : adet;
        float c = __fdividef(0.5f, sdet);
        X00 = 0.5f * X00 + c * C00; X01 = 0.5f * X01 + c * C01; X02 = 0.5f * X02 + c * C02;
        X10 = 0.5f * X10 + c * C10; X11 = 0.5f * X11 + c * C11; X12 = 0.5f * X12 + c * C12;
        X20 = 0.5f * X20 + c * C20; X21 = 0.5f * X21 + c * C21; X22 = 0.5f * X22 + c * C22;
    }

    // ---------- S = R^T M R, lower triangle ----------
    float w0x = m[0]*X00 + m[1]*X10 + m[3]*X20;
    float w0y = m[1]*X00 + m[2]*X10 + m[4]*X20;
    float w0z = m[3]*X00 + m[4]*X10 + m[5]*X20;
    float w1x = m[0]*X01 + m[1]*X11 + m[3]*X21;
    float w1y = m[1]*X01 + m[2]*X11 + m[4]*X21;
    float w1z = m[3]*X01 + m[4]*X11 + m[5]*X21;
    float w2x = m[0]*X02 + m[1]*X12 + m[3]*X22;
    float w2y = m[1]*X02 + m[2]*X12 + m[4]*X22;
    float w2z = m[3]*X02 + m[4]*X12 + m[5]*X22;

    float S00 = X00*w0x + X10*w0y + X20*w0z;
    float S10 = X01*w0x + X11*w0y + X21*w0z;
    float S11 = X01*w1x + X11*w1y + X21*w1z;
    float S20 = X02*w0x + X12*w0y + X22*w0z;
    float S21 = X02*w1x + X12*w1y + X22*w1z;
    float S22 = X02*w2x + X12*w2y + X22*w2z;

    float* o = out + (size_t)b * 6 * HWD + vox;
    o[0]       = S00;
    o[HWD]     = S10;
    o[2 * HWD] = S11;
    o[3 * HWD] = S20;
    o[4 * HWD] = S21;
    o[5 * HWD] = S22;
}

extern "C" void kernel_launch(void* const* d_in, const int* in_sizes, int n_in,
                              void* d_out, int out_size)
{
    const float* dti = (const float*)d_in[0];
    const float* ddf = (const float*)d_in[1];
    int s0 = in_sizes[0], s1 = in_sizes[1];
    if (s0 < s1) { const float* t = dti; dti = ddf; ddf = t; int ts = s0; s0 = s1; s1 = ts; }
    int B = s1 / (3 * HWD);
    if (B > MAXB) B = MAXB;
    int total = B * HWD;
    int threads = 256;
    int blocks = (total + threads - 1) / threads;
    pack_half_kernel<<<blocks, threads>>>(dti, total);
    warp_dti_kernel<<<blocks, threads>>>(ddf, (float*)d_out, total);
}

// round 16
// speedup vs baseline: 2.0823x; 1.0122x over previous
#include <cuda_runtime.h>
#include <cuda_fp16.h>

// WarpDTI fused — R15 structure (measured best): dti pre-packed into 3 planar
// __half2 planes (channel pairs) -> 24-instruction gather at 4B/lane with
// z-contiguous lanes; J/R/output all fp32. R16: prepass vectorized 4 voxels/
// thread (LDG.128/STG.128), polar = 2 scaled + 3 plain Newton (convergence
// floor 2.3e-5 is negligible vs the 2.1e-4 fp16 quantization floor).

constexpr int HWD  = 64 * 64 * 64;   // 262144 = 2^18
constexpr int MAXB = 2;

__device__ __half2 g_dti_h[(size_t)MAXB * 3 * HWD];   // 6.3 MB scratch

__global__ __launch_bounds__(256)
void pack_half_kernel(const float* __restrict__ dti, int total4)
{
    int idx = blockIdx.x * blockDim.x + threadIdx.x;   // one thread = 4 voxels
    if (idx >= total4) return;
    int vox = (idx << 2) & (HWD - 1);
    int b   = idx >> 16;                                // (idx*4) >> 18

    const float* p = dti + (size_t)b * 6 * HWD + vox;
    float4 c0 = __ldg((const float4*)(p));
    float4 c1 = __ldg((const float4*)(p +     HWD));
    float4 c2 = __ldg((const float4*)(p + 2 * HWD));
    float4 c3 = __ldg((const float4*)(p + 3 * HWD));
    float4 c4 = __ldg((const float4*)(p + 4 * HWD));
    float4 c5 = __ldg((const float4*)(p + 5 * HWD));

    __half2* g = g_dti_h + (size_t)b * 3 * HWD;

    __half2 p0[4] = { __floats2half2_rn(c0.x, c1.x), __floats2half2_rn(c0.y, c1.y),
                      __floats2half2_rn(c0.z, c1.z), __floats2half2_rn(c0.w, c1.w) };
    __half2 p1[4] = { __floats2half2_rn(c2.x, c3.x), __floats2half2_rn(c2.y, c3.y),
                      __floats2half2_rn(c2.z, c3.z), __floats2half2_rn(c2.w, c3.w) };
    __half2 p2[4] = { __floats2half2_rn(c4.x, c5.x), __floats2half2_rn(c4.y, c5.y),
                      __floats2half2_rn(c4.z, c5.z), __floats2half2_rn(c4.w, c5.w) };

    *(uint4*)(g +           vox) = *(const uint4*)p0;
    *(uint4*)(g +     HWD + vox) = *(const uint4*)p1;
    *(uint4*)(g + 2 * HWD + vox) = *(const uint4*)p2;
}

__global__ __launch_bounds__(256)
void warp_dti_kernel(const float* __restrict__ ddf,
                     float* __restrict__ out,
                     int total)
{
    int idx = blockIdx.x * blockDim.x + threadIdx.x;
    if (idx >= total) return;

    int vox = idx & (HWD - 1);
    int b   = idx >> 18;
    int z   =  vox        & 63;
    int y   = (vox >> 6)  & 63;
    int x   =  vox >> 12;

    const float* u = ddf + (size_t)b * 3 * HWD;

    float u0 = __ldg(u +           vox);
    float u1 = __ldg(u +     HWD + vox);
    float u2 = __ldg(u + 2 * HWD + vox);

    // ---------- Jacobian J = I + du_i/dx_j (jnp.gradient semantics) --------
    float J00, J01, J02, J10, J11, J12, J20, J21, J22;
    {   // axis 0 (x), stride 4096
        int ip = (x < 63) ? x + 1 : 63;
        int im = (x > 0 ) ? x - 1 : 0;
        float s = (ip - im == 2) ? 0.5f : 1.0f;
        int op = (ip - x) << 12, om = (im - x) << 12;
        J00 = (__ldg(u +           vox + op) - __ldg(u +           vox + om)) * s;
        J10 = (__ldg(u + HWD     + vox + op) - __ldg(u + HWD     + vox + om)) * s;
        J20 = (__ldg(u + 2 * HWD + vox + op) - __ldg(u + 2 * HWD + vox + om)) * s;
    }
    {   // axis 1 (y), stride 64
        int ip = (y < 63) ? y + 1 : 63;
        int im = (y > 0 ) ? y - 1 : 0;
        float s = (ip - im == 2) ? 0.5f : 1.0f;
        int op = (ip - y) << 6, om = (im - y) << 6;
        J01 = (__ldg(u +           vox + op) - __ldg(u +           vox + om)) * s;
        J11 = (__ldg(u + HWD     + vox + op) - __ldg(u + HWD     + vox + om)) * s;
        J21 = (__ldg(u + 2 * HWD + vox + op) - __ldg(u + 2 * HWD + vox + om)) * s;
    }
    {   // axis 2 (z), stride 1
        int ip = (z < 63) ? z + 1 : 63;
        int im = (z > 0 ) ? z - 1 : 0;
        float s = (ip - im == 2) ? 0.5f : 1.0f;
        int op = ip - z, om = im - z;
        J02 = (__ldg(u +           vox + op) - __ldg(u +           vox + om)) * s;
        J12 = (__ldg(u + HWD     + vox + op) - __ldg(u + HWD     + vox + om)) * s;
        J22 = (__ldg(u + 2 * HWD + vox + op) - __ldg(u + 2 * HWD + vox + om)) * s;
    }
    J00 += 1.0f; J11 += 1.0f; J22 += 1.0f;

    // ---------- trilinear warp (border clamp, align_corners) ----------
    float cx = fminf(fmaxf(u0 + (float)x, 0.0f), 63.0f);
    float cy = fminf(fmaxf(u1 + (float)y, 0.0f), 63.0f);
    float cz = fminf(fmaxf(u2 + (float)z, 0.0f), 63.0f);
    float xf = floorf(cx), yf = floorf(cy), zf = floorf(cz);
    float fx = cx - xf,   fy = cy - yf,   fz = cz - zf;
    int x0 = (int)xf, y0 = (int)yf, z0 = (int)zf;
    int x1 = min(x0 + 1, 63), y1 = min(y0 + 1, 63), z1 = min(z0 + 1, 63);

    int c000 = ((((x0 << 6) + y0) << 6)) + z0;
    int c001 = ((((x0 << 6) + y0) << 6)) + z1;
    int c010 = ((((x0 << 6) + y1) << 6)) + z0;
    int c011 = ((((x0 << 6) + y1) << 6)) + z1;
    int c100 = ((((x1 << 6) + y0) << 6)) + z0;
    int c101 = ((((x1 << 6) + y0) << 6)) + z1;
    int c110 = ((((x1 << 6) + y1) << 6)) + z0;
    int c111 = ((((x1 << 6) + y1) << 6)) + z1;

    float wx0 = 1.0f - fx, wy0 = 1.0f - fy, wz0 = 1.0f - fz;
    float w000 = wx0 * wy0 * wz0, w001 = wx0 * wy0 * fz;
    float w010 = wx0 * fy  * wz0, w011 = wx0 * fy  * fz;
    float w100 = fx  * wy0 * wz0, w101 = fx  * wy0 * fz;
    float w110 = fx  * fy  * wz0, w111 = fx  * fy  * fz;

    // ---------- gather: 3 half2 planes x 8 corners = 24 LDG.32 ----------
    float m[6];
    const __half2* img = g_dti_h + (size_t)b * 3 * HWD;
    #pragma unroll
    for (int pl = 0; pl < 3; pl++) {
        const __half2* p = img + (size_t)pl * HWD;
        float2 v000 = __half22float2(__ldg(p + c000));
        float2 v001 = __half22float2(__ldg(p + c001));
        float2 v010 = __half22float2(__ldg(p + c010));
        float2 v011 = __half22float2(__ldg(p + c011));
        float2 v100 = __half22float2(__ldg(p + c100));
        float2 v101 = __half22float2(__ldg(p + c101));
        float2 v110 = __half22float2(__ldg(p + c110));
        float2 v111 = __half22float2(__ldg(p + c111));
        m[2 * pl]     = w000 * v000.x + w001 * v001.x + w010 * v010.x + w011 * v011.x
                      + w100 * v100.x + w101 * v101.x + w110 * v110.x + w111 * v111.x;
        m[2 * pl + 1] = w000 * v000.y + w001 * v001.y + w010 * v010.y + w011 * v011.y
                      + w100 * v100.y + w101 * v101.y + w110 * v110.y + w111 * v111.y;
    }

    // ---------- polar factor R = U V^T ----------
    float X00 = J00, X01 = J01, X02 = J02;
    float X10 = J10, X11 = J11, X12 = J12;
    float X20 = J20, X21 = J21, X22 = J22;

    // 2 scaled Newton iterations (Frobenius mu, fast-math — self-correcting)
    #pragma unroll
    for (int it = 0; it < 2; ++it) {
        float C00 = X11 * X22 - X12 * X21;
        float C01 = X12 * X20 - X10 * X22;
        float C02 = X10 * X21 - X11 * X20;
        float C10 = X21 * X02 - X22 * X01;
        float C11 = X22 * X00 - X20 * X02;
        float C12 = X20 * X01 - X21 * X00;
        float C20 = X01 * X12 - X02 * X11;
        float C21 = X02 * X10 - X00 * X12;
        float C22 = X00 * X11 - X01 * X10;
        float det = X00 * C00 + X01 * C01 + X02 * C02;
        float adet = fmaxf(fabsf(det), 1e-12f);
        float sdet = (det < 0.0f) ? -adet : adet;
        float nX = X00*X00 + X01*X01 + X02*X02 + X10*X10 + X11*X11 + X12*X12
                 + X20*X20 + X21*X21 + X22*X22;
        float nC = C00*C00 + C01*C01 + C02*C02 + C10*C10 + C11*C11 + C12*C12
                 + C20*C20 + C21*C21 + C22*C22;
        float mu = exp2f(0.25f * __log2f(nC / nX)) * rsqrtf(adet);
        mu = fminf(fmaxf(mu, 1e-4f), 1e4f);
        float a = 0.5f * mu;
        float c = __fdividef(0.5f, mu * sdet);
        X00 = a * X00 + c * C00; X01 = a * X01 + c * C01; X02 = a * X02 + c * C02;
        X10 = a * X10 + c * C10; X11 = a * X11 + c * C11; X12 = a * X12 + c * C12;
        X20 = a * X20 + c * C20; X21 = a * X21 + c * C21; X22 = a * X22 + c * C22;
    }
    // 3 plain Newton iterations: X <- 0.5*(X + cof(X)/det)
    #pragma unroll
    for (int it = 0; it < 3; ++it) {
        float C00 = X11 * X22 - X12 * X21;
        float C01 = X12 * X20 - X10 * X22;
        float C02 = X10 * X21 - X11 * X20;
        float C10 = X21 * X02 - X22 * X01;
        float C11 = X22 * X00 - X20 * X02;
        float C12 = X20 * X01 - X21 * X00;
        float C20 = X01 * X12 - X02 * X11;
        float C21 = X02 * X10 - X00 * X12;
        float C22 = X00 * X11 - X01 * X10;
        float det = X00 * C00 + X01 * C01 + X02 * C02;
        float adet = fmaxf(fabsf(det), 1e-12f);
        float sdet = (det < 0.0f) ? -adet : adet;
        float c = __fdividef(0.5f, sdet);
        X00 = 0.5f * X00 + c * C00; X01 = 0.5f * X01 + c * C01; X02 = 0.5f * X02 + c * C02;
        X10 = 0.5f * X10 + c * C10; X11 = 0.5f * X11 + c * C11; X12 = 0.5f * X12 + c * C12;
        X20 = 0.5f * X20 + c * C20; X21 = 0.5f * X21 + c * C21; X22 = 0.5f * X22 + c * C22;
    }

    // ---------- S = R^T M R, lower triangle ----------
    float w0x = m[0]*X00 + m[1]*X10 + m[3]*X20;
    float w0y = m[1]*X00 + m[2]*X10 + m[4]*X20;
    float w0z = m[3]*X00 + m[4]*X10 + m[5]*X20;
    float w1x = m[0]*X01 + m[1]*X11 + m[3]*X21;
    float w1y = m[1]*X01 + m[2]*X11 + m[4]*X21;
    float w1z = m[3]*X01 + m[4]*X11 + m[5]*X21;
    float w2x = m[0]*X02 + m[1]*X12 + m[3]*X22;
    float w2y = m[1]*X02 + m[2]*X12 + m[4]*X22;
    float w2z = m[3]*X02 + m[4]*X12 + m[5]*X22;

    float S00 = X00*w0x + X10*w0y + X20*w0z;
    float S10 = X01*w0x + X11*w0y + X21*w0z;
    float S11 = X01*w1x + X11*w1y + X21*w1z;
    float S20 = X02*w0x + X12*w0y + X22*w0z;
    float S21 = X02*w1x + X12*w1y + X22*w1z;
    float S22 = X02*w2x + X12*w2y + X22*w2z;

    float* o = out + (size_t)b * 6 * HWD + vox;
    o[0]       = S00;
    o[HWD]     = S10;
    o[2 * HWD] = S11;
    o[3 * HWD] = S20;
    o[4 * HWD] = S21;
    o[5 * HWD] = S22;
}

extern "C" void kernel_launch(void* const* d_in, const int* in_sizes, int n_in,
                              void* d_out, int out_size)
{
    const float* dti = (const float*)d_in[0];
    const float* ddf = (const float*)d_in[1];
    int s0 = in_sizes[0], s1 = in_sizes[1];
    if (s0 < s1) { const float* t = dti; dti = ddf; ddf = t; int ts = s0; s0 = s1; s1 = ts; }
    int B = s1 / (3 * HWD);
    if (B > MAXB) B = MAXB;
    int total  = B * HWD;
    int total4 = total >> 2;
    int threads = 256;
    pack_half_kernel<<<(total4 + threads - 1) / threads, threads>>>(dti, total4);
    warp_dti_kernel<<<(total  + threads - 1) / threads, threads>>>(ddf, (float*)d_out, total);
}